// round 15
// baseline (speedup 1.0000x reference)
#include <cuda_runtime.h>
#include <cuda_bf16.h>
#include <cstdint>

#define B_  4
#define N_  4096
#define TM  128
#define TN  128

// smem layout (byte offsets). Row stride 272B -> conflict-free ldmatrix.
#define LDST    272
#define A_OFF   0
#define B0_OFF  (128 * LDST)
#define B1_OFF  (2 * 128 * LDST)
#define RSB0_OFF (3 * 128 * LDST)      // staged RS for B strip, ring [2][128] f32
#define RSB1_OFF (RSB0_OFF + 512)
#define RS_OFF   (RSB1_OFF + 512)      // cross-warp rowsum flush [2][128]
#define SMEM_BYTES (RS_OFF + 1024)

// Pre-converted hi/lo bf16 operands: row r -> [hi 64 bf16 | lo 64 bf16] = 256B
__device__ __align__(16) __nv_bfloat16 XHL[B_ * N_ * 128];
__device__ float RSg[B_ * N_];          // row sums of g (written once by pass A)
__device__ float CGg[B_ * N_];          // exact row self-dots c_n = ||x_n||^2 (fp32)

static __device__ __forceinline__ float ex2a(float x) {
    float y; asm("ex2.approx.f32 %0, %1;" : "=f"(y) : "f"(x)); return y;
}
static __device__ __forceinline__ float rcpa(float x) {
    float y; asm("rcp.approx.f32 %0, %1;" : "=f"(y) : "f"(x)); return y;
}

static __device__ __forceinline__ void ldsm_x4(uint32_t addr, uint32_t r[4]) {
    asm volatile("ldmatrix.sync.aligned.m8n8.x4.shared.b16 {%0,%1,%2,%3}, [%4];"
                 : "=r"(r[0]), "=r"(r[1]), "=r"(r[2]), "=r"(r[3]) : "r"(addr));
}
static __device__ __forceinline__ void mma16816(float d[4], const uint32_t a[4],
                                                uint32_t b0, uint32_t b1) {
    asm("mma.sync.aligned.m16n8k16.row.col.f32.bf16.bf16.f32 "
        "{%0,%1,%2,%3}, {%4,%5,%6,%7}, {%8,%9}, {%0,%1,%2,%3};"
        : "+f"(d[0]), "+f"(d[1]), "+f"(d[2]), "+f"(d[3])
        : "r"(a[0]), "r"(a[1]), "r"(a[2]), "r"(a[3]), "r"(b0), "r"(b1));
}
#define CP16(dst, src) \
    asm volatile("cp.async.cg.shared.global [%0], [%1], 16;" :: "r"(dst), "l"(src))
#define CP_COMMIT() asm volatile("cp.async.commit_group;" ::: "memory")
#define CP_WAIT(n)  asm volatile("cp.async.wait_group %0;" :: "n"(n) : "memory")

static __device__ __forceinline__ void stage_tile(uint32_t dstbase,
                                                  const __nv_bfloat16* src, int tid) {
    #pragma unroll
    for (int i = 0; i < 8; i++) {
        int v = tid + i * 256;
        int row = v >> 4, c = v & 15;
        CP16(dstbase + (uint32_t)row * LDST + c * 16,
             (const void*)(src + (size_t)row * 128 + c * 8));
    }
}
static __device__ __forceinline__ void stage_rs(uint32_t dstbase,
                                                const float* src, int tid) {
    if (tid < 32) CP16(dstbase + tid * 16, (const void*)(src + tid * 4));
}

// ======= prologue: fp32 -> hi/lo bf16, self-dot (eighth-row per thread) =======
__global__ __launch_bounds__(256, 8)
void convert_kernel(const float* __restrict__ X) {
    int v = blockIdx.x * 256 + threadIdx.x;     // 131072 threads
    int row = v >> 3;
    int q   = v & 7;                            // eighth of the row (8 elems)
    const float* rp = X + (size_t)row * 64 + q * 8;
    uint32_t hp[4], lp[4];
    float c = 0.f;
    #pragma unroll
    for (int k4 = 0; k4 < 2; k4++) {
        float4 val = *(const float4*)(rp + k4 * 4);
        c = fmaf(val.x, val.x, c); c = fmaf(val.y, val.y, c);
        c = fmaf(val.z, val.z, c); c = fmaf(val.w, val.w, c);
        __nv_bfloat16 h0 = __float2bfloat16(val.x), h1 = __float2bfloat16(val.y);
        __nv_bfloat16 h2 = __float2bfloat16(val.z), h3 = __float2bfloat16(val.w);
        union { __nv_bfloat162 v2; uint32_t u; } c0, c1, c2, c3;
        c0.v2 = __halves2bfloat162(h0, h1);
        c1.v2 = __halves2bfloat162(h2, h3);
        c2.v2 = __halves2bfloat162(__float2bfloat16(val.x - __bfloat162float(h0)),
                                   __float2bfloat16(val.y - __bfloat162float(h1)));
        c3.v2 = __halves2bfloat162(__float2bfloat16(val.z - __bfloat162float(h2)),
                                   __float2bfloat16(val.w - __bfloat162float(h3)));
        hp[k4 * 2] = c0.u; hp[k4 * 2 + 1] = c1.u;
        lp[k4 * 2] = c2.u; lp[k4 * 2 + 1] = c3.u;
    }
    // combine row self-dot across the 8 eighth-threads (same warp)
    c += __shfl_xor_sync(0xffffffffu, c, 1);
    c += __shfl_xor_sync(0xffffffffu, c, 2);
    c += __shfl_xor_sync(0xffffffffu, c, 4);
    uint4* dst = (uint4*)(XHL + (size_t)row * 128);
    dst[q]     = make_uint4(hp[0], hp[1], hp[2], hp[3]);
    dst[8 + q] = make_uint4(lp[0], lp[1], lp[2], lp[3]);
    if (q == 0) CGg[row] = c;
}

// ================= pass A: hi-only GEMM over ALL tiles, row sums only =========
// Diagonal dominance: off-diag mass <= ~1e-3 of any row sum, so hi-only
// precision suffices there; the diagonal element is substituted exactly (c_n).
// No mirroring -> no shfl colsum reductions, no atomics; RSg written once.
__global__ __launch_bounds__(256, 1)
void rowsum_kernel() {
    extern __shared__ __align__(16) char sm[];
    const uint32_t sbase = (uint32_t)__cvta_generic_to_shared(sm);

    const int tid = threadIdx.x;
    const int wid = tid >> 5;
    const int lane = tid & 31;
    const int b = blockIdx.x >> 5;
    const int i = blockIdx.x & 31;
    const int r0 = i * TM;
    const __nv_bfloat16* Xb = XHL + (size_t)b * N_ * 128;

    stage_tile(sbase + A_OFF, Xb + (size_t)r0 * 128, tid);
    stage_tile(sbase + B0_OFF, Xb + (size_t)r0 * 128, tid);  // tile dt=0 is strip i
    CP_COMMIT();

    const int mblk = (wid & 3) * 32;
    const int nhalf = wid >> 2;
    const int nblk = nhalf * 64;
    const int g8  = lane >> 3;
    const int rowoff = (g8 & 1) * 8 + (lane & 7);
    const int kch8   = (g8 >> 1) * 8;
    const int g4  = lane >> 2;
    const int col2 = (lane & 3) * 2;

    const uint32_t a_base0 = sbase + A_OFF + (uint32_t)(mblk + rowoff) * LDST + kch8 * 2;
    const uint32_t a_base1 = a_base0 + 16u * LDST;
    const uint32_t bb_base = (uint32_t)(nblk + rowoff) * LDST + kch8 * 2;

    const float L2E  = 1.4426950408889634f;
    const float NEGS = -60.0f * L2E;

    float cA[2], cB[2];
    {
        const float* CGb = CGg + b * N_;
        #pragma unroll
        for (int mt = 0; mt < 2; mt++) {
            cA[mt] = CGb[r0 + mblk + mt * 16 + g4];
            cB[mt] = CGb[r0 + mblk + mt * 16 + g4 + 8];
        }
    }

    CP_WAIT(0);
    __syncthreads();

    uint32_t ah[2][4][4];
    #pragma unroll
    for (int ks = 0; ks < 4; ks++) {
        ldsm_x4(a_base0 + ks * 32, ah[0][ks]);
        ldsm_x4(a_base1 + ks * 32, ah[1][ks]);
    }

    float sumA[2] = {0.f, 0.f}, sumB[2] = {0.f, 0.f};

    #pragma unroll 1
    for (int dt = 0; dt < 32; dt++) {
        CP_WAIT(0);
        __syncthreads();
        if (dt + 1 < 32) {
            const int jn = (i + dt + 1) & 31;
            stage_tile(sbase + (((dt + 1) & 1) ? B1_OFF : B0_OFF),
                       Xb + (size_t)jn * TN * 128, tid);
            CP_COMMIT();
        }

        const uint32_t b_base = sbase + ((dt & 1) ? B1_OFF : B0_OFF) + bb_base;

        float acc[2][8][4];
        #pragma unroll
        for (int mt = 0; mt < 2; mt++)
            #pragma unroll
            for (int nt = 0; nt < 8; nt++)
                #pragma unroll
                for (int e = 0; e < 4; e++) acc[mt][nt][e] = 0.f;

        // hi-only GEMM: 4 k-groups
        uint32_t bbA[4][4], bbB[4][4];
        #pragma unroll
        for (int p = 0; p < 4; p++) ldsm_x4(b_base + (uint32_t)(p * 16) * LDST, bbA[p]);
        #pragma unroll
        for (int g = 0; g < 4; g++) {
            uint32_t (*cur)[4] = (g & 1) ? bbB : bbA;
            uint32_t (*nxt)[4] = (g & 1) ? bbA : bbB;
            if (g + 1 < 4) {
                #pragma unroll
                for (int p = 0; p < 4; p++)
                    ldsm_x4(b_base + (uint32_t)(p * 16) * LDST + (g + 1) * 32, nxt[p]);
            }
            #pragma unroll
            for (int p = 0; p < 4; p++) {
                mma16816(acc[0][2*p],   ah[0][g], cur[p][0], cur[p][2]);
                mma16816(acc[0][2*p+1], ah[0][g], cur[p][1], cur[p][3]);
                mma16816(acc[1][2*p],   ah[1][g], cur[p][0], cur[p][2]);
                mma16816(acc[1][2*p+1], ah[1][g], cur[p][1], cur[p][3]);
            }
        }

        const bool diag = (dt == 0);
        #pragma unroll
        for (int mt = 0; mt < 2; mt++) {
            const int rAi = mblk + mt * 16 + g4;
            const int rBi = rAi + 8;
            #pragma unroll
            for (int nt = 0; nt < 8; nt++) {
                float s0 = acc[mt][nt][0], s1 = acc[mt][nt][1];
                float s2 = acc[mt][nt][2], s3 = acc[mt][nt][3];
                if (diag) {
                    const int c0i = nblk + nt * 8 + col2;
                    const int c1i = c0i + 1;
                    if (c0i == rAi) s0 = cA[mt];
                    if (c1i == rAi) s1 = cA[mt];
                    if (c0i == rBi) s2 = cB[mt];
                    if (c1i == rBi) s3 = cB[mt];
                }
                sumA[mt] += ex2a(fmaf(s0, L2E, NEGS)) + ex2a(fmaf(s1, L2E, NEGS));
                sumB[mt] += ex2a(fmaf(s2, L2E, NEGS)) + ex2a(fmaf(s3, L2E, NEGS));
            }
        }
    }

    // ---- reduce over lane quads + 2 N-half warps, plain store ----
    float* rsum = (float*)(sm + RS_OFF);
    __syncthreads();
    #pragma unroll
    for (int mt = 0; mt < 2; mt++) {
        float sA = sumA[mt], sB = sumB[mt];
        sA += __shfl_xor_sync(0xffffffffu, sA, 1);
        sA += __shfl_xor_sync(0xffffffffu, sA, 2);
        sB += __shfl_xor_sync(0xffffffffu, sB, 1);
        sB += __shfl_xor_sync(0xffffffffu, sB, 2);
        if ((lane & 3) == 0) {
            rsum[nhalf * 128 + mblk + mt * 16 + g4]     = sA;
            rsum[nhalf * 128 + mblk + mt * 16 + g4 + 8] = sB;
        }
    }
    __syncthreads();
    if (tid < TM)
        RSg[(size_t)b * N_ + r0 + tid] = rsum[tid] + rsum[128 + tid];
}

// ================= pass B: symmetric full-precision, normalize + mirror =======
__global__ __launch_bounds__(256, 1)
void passb_kernel(float* __restrict__ out) {
    extern __shared__ __align__(16) char sm[];
    const uint32_t sbase = (uint32_t)__cvta_generic_to_shared(sm);

    const int tid = threadIdx.x;
    const int wid = tid >> 5;
    const int lane = tid & 31;
    const int b = blockIdx.x >> 5;
    const int i = blockIdx.x & 31;
    const int r0 = i * TM;
    const __nv_bfloat16* Xb = XHL + (size_t)b * N_ * 128;
    const float* RSb = RSg + b * N_;
    const int ntile = (i < 16) ? 17 : 16;

    stage_tile(sbase + A_OFF, Xb + (size_t)r0 * 128, tid);
    stage_tile(sbase + B0_OFF, Xb + (size_t)r0 * 128, tid);
    stage_rs(sbase + RSB0_OFF, RSb + r0, tid);
    CP_COMMIT();
    CP_WAIT(0);
    __syncthreads();

    const int mblk = (wid & 3) * 32;
    const int nhalf = wid >> 2;
    const int nblk = nhalf * 64;
    const int g8  = lane >> 3;
    const int rowoff = (g8 & 1) * 8 + (lane & 7);
    const int kch8   = (g8 >> 1) * 8;
    const int g4  = lane >> 2;
    const int col2 = (lane & 3) * 2;

    const uint32_t a_base0 = sbase + A_OFF + (uint32_t)(mblk + rowoff) * LDST + kch8 * 2;
    const uint32_t a_base1 = a_base0 + 16u * LDST;
    const uint32_t bb_base = (uint32_t)(nblk + rowoff) * LDST + kch8 * 2;

    uint32_t ah[2][4][4], al[2][4][4];
    #pragma unroll
    for (int ks = 0; ks < 4; ks++) {
        ldsm_x4(a_base0 + ks * 32,       ah[0][ks]);
        ldsm_x4(a_base1 + ks * 32,       ah[1][ks]);
        ldsm_x4(a_base0 + 128 + ks * 32, al[0][ks]);
        ldsm_x4(a_base1 + 128 + ks * 32, al[1][ks]);
    }

    const float L2E  = 1.4426950408889634f;
    const float NEGS = -60.0f * L2E;

    float zrA[2], zrB[2];
    #pragma unroll
    for (int mt = 0; mt < 2; mt++) {
        zrA[mt] = rcpa(RSb[r0 + mblk + mt * 16 + g4]);
        zrB[mt] = rcpa(RSb[r0 + mblk + mt * 16 + g4 + 8]);
    }

    const size_t orow0 = (size_t)(b * N_ + r0 + mblk + g4) * N_;

    #pragma unroll 1
    for (int dt = 0; dt < ntile; dt++) {
        const int j = (i + dt) & 31;
        CP_WAIT(0);
        __syncthreads();
        if (dt + 1 < ntile) {
            const int jn = (i + dt + 1) & 31;
            stage_tile(sbase + (((dt + 1) & 1) ? B1_OFF : B0_OFF),
                       Xb + (size_t)jn * TN * 128, tid);
            stage_rs(sbase + (((dt + 1) & 1) ? RSB1_OFF : RSB0_OFF), RSb + jn * 128, tid);
            CP_COMMIT();
        }

        const uint32_t b_base = sbase + ((dt & 1) ? B1_OFF : B0_OFF) + bb_base;

        float acc[2][8][4];
        #pragma unroll
        for (int mt = 0; mt < 2; mt++)
            #pragma unroll
            for (int nt = 0; nt < 8; nt++)
                #pragma unroll
                for (int e = 0; e < 4; e++) acc[mt][nt][e] = 0.f;

        // full pipelined GEMM (hi.hi + lo.hi + hi.lo)
        uint32_t bbA[4][4], bbB[4][4];
        #pragma unroll
        for (int p = 0; p < 4; p++) ldsm_x4(b_base + (uint32_t)(p * 16) * LDST, bbA[p]);
        #pragma unroll
        for (int g = 0; g < 8; g++) {
            uint32_t (*cur)[4] = (g & 1) ? bbB : bbA;
            uint32_t (*nxt)[4] = (g & 1) ? bbA : bbB;
            if (g + 1 < 8) {
                const int gn = g + 1;
                const uint32_t off = (gn < 4) ? (uint32_t)(gn * 32)
                                              : (uint32_t)(128 + (gn - 4) * 32);
                #pragma unroll
                for (int p = 0; p < 4; p++)
                    ldsm_x4(b_base + (uint32_t)(p * 16) * LDST + off, nxt[p]);
            }
            if (g < 4) {
                const int ks = g;
                #pragma unroll
                for (int p = 0; p < 4; p++) {
                    mma16816(acc[0][2*p],   ah[0][ks], cur[p][0], cur[p][2]);
                    mma16816(acc[0][2*p+1], ah[0][ks], cur[p][1], cur[p][3]);
                    mma16816(acc[1][2*p],   ah[1][ks], cur[p][0], cur[p][2]);
                    mma16816(acc[1][2*p+1], ah[1][ks], cur[p][1], cur[p][3]);
                }
                #pragma unroll
                for (int p = 0; p < 4; p++) {
                    mma16816(acc[0][2*p],   al[0][ks], cur[p][0], cur[p][2]);
                    mma16816(acc[0][2*p+1], al[0][ks], cur[p][1], cur[p][3]);
                    mma16816(acc[1][2*p],   al[1][ks], cur[p][0], cur[p][2]);
                    mma16816(acc[1][2*p+1], al[1][ks], cur[p][1], cur[p][3]);
                }
            } else {
                const int ks = g - 4;
                #pragma unroll
                for (int p = 0; p < 4; p++) {
                    mma16816(acc[0][2*p],   ah[0][ks], cur[p][0], cur[p][2]);
                    mma16816(acc[0][2*p+1], ah[0][ks], cur[p][1], cur[p][3]);
                    mma16816(acc[1][2*p],   ah[1][ks], cur[p][0], cur[p][2]);
                    mma16816(acc[1][2*p+1], ah[1][ks], cur[p][1], cur[p][3]);
                }
            }
        }

        const bool diag = (dt == 0);
        const float* rsb = (const float*)(sm + ((dt & 1) ? RSB1_OFF : RSB0_OFF));
        const int colbase = j * 128 + nblk + col2;
        float* om = out + (size_t)(b * N_ + j * 128 + nblk + col2) * N_
                        + r0 + mblk + g4;
        #pragma unroll
        for (int nt = 0; nt < 8; nt++) {
            float zc0 = 0.f, zc1 = 0.f;
            if (!diag) {
                float2 rv = *(const float2*)&rsb[nblk + col2 + nt * 8];
                zc0 = rcpa(rv.x);
                zc1 = rcpa(rv.y);
            }
            #pragma unroll
            for (int mt = 0; mt < 2; mt++) {
                float g0 = ex2a(fmaf(acc[mt][nt][0], L2E, NEGS));
                float g1 = ex2a(fmaf(acc[mt][nt][1], L2E, NEGS));
                float g2 = ex2a(fmaf(acc[mt][nt][2], L2E, NEGS));
                float g3 = ex2a(fmaf(acc[mt][nt][3], L2E, NEGS));
                float* o1 = out + orow0 + (size_t)(mt * 16) * N_ + colbase + nt * 8;
                *(float2*)o1                    = make_float2(g0 * zrA[mt], g1 * zrA[mt]);
                *(float2*)(o1 + (size_t)8 * N_) = make_float2(g2 * zrB[mt], g3 * zrB[mt]);
                if (!diag) {
                    float* m1 = om + (size_t)(nt * 8) * N_ + mt * 16;
                    m1[0]       = g0 * zc0;
                    m1[N_]      = g1 * zc1;
                    m1[8]       = g2 * zc0;
                    m1[N_ + 8]  = g3 * zc1;
                }
            }
        }
    }
}

extern "C" void kernel_launch(void* const* d_in, const int* in_sizes, int n_in,
                              void* d_out, int out_size) {
    const float* X = (const float*)d_in[0];
    float* out = (float*)d_out;
    convert_kernel<<<B_ * N_ * 8 / 256, 256>>>(X);
    cudaFuncSetAttribute(rowsum_kernel,
                         cudaFuncAttributeMaxDynamicSharedMemorySize, SMEM_BYTES);
    cudaFuncSetAttribute(passb_kernel,
                         cudaFuncAttributeMaxDynamicSharedMemorySize, SMEM_BYTES);
    rowsum_kernel<<<B_ * 32, 256, SMEM_BYTES>>>();
    passb_kernel<<<B_ * 32, 256, SMEM_BYTES>>>(out);
}

// round 16
// speedup vs baseline: 1.0865x; 1.0865x over previous
#include <cuda_runtime.h>
#include <cuda_bf16.h>
#include <cstdint>

#define B_  4
#define N_  4096
#define TM  128
#define TN  128

// smem layout (byte offsets). Row stride 272B -> conflict-free ldmatrix.
#define LDST    272
#define A_OFF   0
#define B0_OFF  (128 * LDST)
#define B1_OFF  (2 * 128 * LDST)
#define RSB0_OFF (3 * 128 * LDST)
#define RSB1_OFF (RSB0_OFF + 512)
#define RS_OFF   (RSB1_OFF + 512)
#define SMEM_BYTES (RS_OFF + 1024)

__device__ __align__(16) __nv_bfloat16 XHL[B_ * N_ * 128];
__device__ float RSg[B_ * N_];
__device__ float CGg[B_ * N_];
__device__ unsigned int gbars[8];   // [b]: phase0->1, [4+b]: phase1->2 (monotonic)

static __device__ __forceinline__ float ex2a(float x) {
    float y; asm("ex2.approx.f32 %0, %1;" : "=f"(y) : "f"(x)); return y;
}
static __device__ __forceinline__ float rcpa(float x) {
    float y; asm("rcp.approx.f32 %0, %1;" : "=f"(y) : "f"(x)); return y;
}
static __device__ __forceinline__ void ldsm_x4(uint32_t addr, uint32_t r[4]) {
    asm volatile("ldmatrix.sync.aligned.m8n8.x4.shared.b16 {%0,%1,%2,%3}, [%4];"
                 : "=r"(r[0]), "=r"(r[1]), "=r"(r[2]), "=r"(r[3]) : "r"(addr));
}
static __device__ __forceinline__ void mma16816(float d[4], const uint32_t a[4],
                                                uint32_t b0, uint32_t b1) {
    asm("mma.sync.aligned.m16n8k16.row.col.f32.bf16.bf16.f32 "
        "{%0,%1,%2,%3}, {%4,%5,%6,%7}, {%8,%9}, {%0,%1,%2,%3};"
        : "+f"(d[0]), "+f"(d[1]), "+f"(d[2]), "+f"(d[3])
        : "r"(a[0]), "r"(a[1]), "r"(a[2]), "r"(a[3]), "r"(b0), "r"(b1));
}
#define CP16(dst, src) \
    asm volatile("cp.async.cg.shared.global [%0], [%1], 16;" :: "r"(dst), "l"(src))
#define CP_COMMIT() asm volatile("cp.async.commit_group;" ::: "memory")
#define CP_WAIT(n)  asm volatile("cp.async.wait_group %0;" :: "n"(n) : "memory")

static __device__ __forceinline__ void stage_tile(uint32_t dstbase,
                                                  const __nv_bfloat16* src, int tid) {
    #pragma unroll
    for (int i = 0; i < 8; i++) {
        int v = tid + i * 256;
        int row = v >> 4, c = v & 15;
        CP16(dstbase + (uint32_t)row * LDST + c * 16,
             (const void*)(src + (size_t)row * 128 + c * 8));
    }
}
static __device__ __forceinline__ void stage_rs(uint32_t dstbase,
                                                const float* src, int tid) {
    if (tid < 32) CP16(dstbase + tid * 16, (const void*)(src + tid * 4));
}

// Device-wide per-batch barrier (32 CTAs each). Monotonic counter with
// generation arithmetic -> correct across CUDA-graph replays without reset.
// All 128 CTAs are resident (grid <= SM count, 1 CTA/SM) so spinning is safe.
static __device__ __forceinline__ void batch_barrier(unsigned int* ctr) {
    __threadfence();
    __syncthreads();
    if (threadIdx.x == 0) {
        unsigned int t = atomicAdd(ctr, 1);
        unsigned int target = (t / 32u + 1u) * 32u;
        while (*(volatile unsigned int*)ctr < target) __nanosleep(64);
        __threadfence();
    }
    __syncthreads();
}

__global__ __launch_bounds__(256, 1)
void fused_kernel(const float* __restrict__ X, float* __restrict__ out) {
    extern __shared__ __align__(16) char sm[];
    const uint32_t sbase = (uint32_t)__cvta_generic_to_shared(sm);

    const int tid = threadIdx.x;
    const int wid = tid >> 5;
    const int lane = tid & 31;
    const int b = blockIdx.x >> 5;
    const int i = blockIdx.x & 31;
    const int r0 = i * TM;
    const __nv_bfloat16* Xb = XHL + (size_t)b * N_ * 128;
    const float* RSb = RSg + b * N_;
    const int ntile = (i < 16) ? 17 : 16;

    // ================= phase 0: convert own strip (128 rows) =================
    {
        const int rl = tid >> 1;          // local row 0..127
        const int q  = tid & 1;           // half-row (32 elems)
        const size_t row = (size_t)b * N_ + r0 + rl;
        const float* rp = X + row * 64 + q * 32;
        uint32_t hp[16], lp[16];
        float c = 0.f;
        #pragma unroll
        for (int k4 = 0; k4 < 8; k4++) {
            float4 val = *(const float4*)(rp + k4 * 4);
            c = fmaf(val.x, val.x, c); c = fmaf(val.y, val.y, c);
            c = fmaf(val.z, val.z, c); c = fmaf(val.w, val.w, c);
            __nv_bfloat16 h0 = __float2bfloat16(val.x), h1 = __float2bfloat16(val.y);
            __nv_bfloat16 h2 = __float2bfloat16(val.z), h3 = __float2bfloat16(val.w);
            union { __nv_bfloat162 v2; uint32_t u; } c0, c1, c2, c3;
            c0.v2 = __halves2bfloat162(h0, h1);
            c1.v2 = __halves2bfloat162(h2, h3);
            c2.v2 = __halves2bfloat162(__float2bfloat16(val.x - __bfloat162float(h0)),
                                       __float2bfloat16(val.y - __bfloat162float(h1)));
            c3.v2 = __halves2bfloat162(__float2bfloat16(val.z - __bfloat162float(h2)),
                                       __float2bfloat16(val.w - __bfloat162float(h3)));
            hp[k4 * 2] = c0.u; hp[k4 * 2 + 1] = c1.u;
            lp[k4 * 2] = c2.u; lp[k4 * 2 + 1] = c3.u;
        }
        c += __shfl_xor_sync(0xffffffffu, c, 1);
        uint4* dst = (uint4*)(XHL + row * 128);
        #pragma unroll
        for (int jj = 0; jj < 4; jj++)
            dst[q * 4 + jj] = make_uint4(hp[4*jj], hp[4*jj+1], hp[4*jj+2], hp[4*jj+3]);
        #pragma unroll
        for (int jj = 0; jj < 4; jj++)
            dst[8 + q * 4 + jj] = make_uint4(lp[4*jj], lp[4*jj+1], lp[4*jj+2], lp[4*jj+3]);
        if (q == 0) { CGg[row] = c; RSg[row] = 0.0f; }
    }
    batch_barrier(&gbars[b]);   // all of batch b's XHL/CGg/RSg(0) visible

    // ---- shared per-warp geometry ----
    const int mblk = (wid & 3) * 32;
    const int nhalf = wid >> 2;
    const int nblk = nhalf * 64;
    const int g8  = lane >> 3;
    const int rowoff = (g8 & 1) * 8 + (lane & 7);
    const int kch8   = (g8 >> 1) * 8;
    const int g4  = lane >> 2;
    const int col2 = (lane & 3) * 2;

    const uint32_t a_base0 = sbase + A_OFF + (uint32_t)(mblk + rowoff) * LDST + kch8 * 2;
    const uint32_t a_base1 = a_base0 + 16u * LDST;
    const uint32_t bb_base = (uint32_t)(nblk + rowoff) * LDST + kch8 * 2;

    const float L2E  = 1.4426950408889634f;
    const float NEGS = -60.0f * L2E;

    // ================= phase 1: mirrored hi-only rowsum pass =================
    // Stage A strip once; diagonal tile (dt=0) aliases it — no B0 copy needed.
    stage_tile(sbase + A_OFF, Xb + (size_t)r0 * 128, tid);
    CP_COMMIT();

    float cA[2], cB[2];
    {
        const float* CGb = CGg + b * N_;
        #pragma unroll
        for (int mt = 0; mt < 2; mt++) {
            cA[mt] = CGb[r0 + mblk + mt * 16 + g4];
            cB[mt] = CGb[r0 + mblk + mt * 16 + g4 + 8];
        }
    }
    CP_WAIT(0);
    __syncthreads();

    uint32_t ah[2][4][4];
    #pragma unroll
    for (int ks = 0; ks < 4; ks++) {
        ldsm_x4(a_base0 + ks * 32, ah[0][ks]);
        ldsm_x4(a_base1 + ks * 32, ah[1][ks]);
    }

    float sumA[2] = {0.f, 0.f}, sumB[2] = {0.f, 0.f};

    #pragma unroll 1
    for (int dt = 0; dt < ntile; dt++) {
        const int j = (i + dt) & 31;
        CP_WAIT(0);
        __syncthreads();
        if (dt + 1 < ntile) {
            const int jn = (i + dt + 1) & 31;
            stage_tile(sbase + (((dt + 1) & 1) ? B1_OFF : B0_OFF),
                       Xb + (size_t)jn * TN * 128, tid);
            CP_COMMIT();
        }

        const uint32_t b_base = (dt == 0 ? sbase + A_OFF
                                         : sbase + ((dt & 1) ? B1_OFF : B0_OFF)) + bb_base;

        float acc[2][8][4];
        #pragma unroll
        for (int mt = 0; mt < 2; mt++)
            #pragma unroll
            for (int nt = 0; nt < 8; nt++)
                #pragma unroll
                for (int e = 0; e < 4; e++) acc[mt][nt][e] = 0.f;

        // hi-only GEMM: 4 k-groups
        uint32_t bbA[4][4], bbB[4][4];
        #pragma unroll
        for (int p = 0; p < 4; p++) ldsm_x4(b_base + (uint32_t)(p * 16) * LDST, bbA[p]);
        #pragma unroll
        for (int g = 0; g < 4; g++) {
            uint32_t (*cur)[4] = (g & 1) ? bbB : bbA;
            uint32_t (*nxt)[4] = (g & 1) ? bbA : bbB;
            if (g + 1 < 4) {
                #pragma unroll
                for (int p = 0; p < 4; p++)
                    ldsm_x4(b_base + (uint32_t)(p * 16) * LDST + (g + 1) * 32, nxt[p]);
            }
            #pragma unroll
            for (int p = 0; p < 4; p++) {
                mma16816(acc[0][2*p],   ah[0][g], cur[p][0], cur[p][2]);
                mma16816(acc[0][2*p+1], ah[0][g], cur[p][1], cur[p][3]);
                mma16816(acc[1][2*p],   ah[1][g], cur[p][0], cur[p][2]);
                mma16816(acc[1][2*p+1], ah[1][g], cur[p][1], cur[p][3]);
            }
        }

        const bool diag = (dt == 0);
        float colp[8][2];
        #pragma unroll
        for (int nt = 0; nt < 8; nt++) { colp[nt][0] = 0.f; colp[nt][1] = 0.f; }
        #pragma unroll
        for (int mt = 0; mt < 2; mt++) {
            const int rAi = mblk + mt * 16 + g4;
            const int rBi = rAi + 8;
            #pragma unroll
            for (int nt = 0; nt < 8; nt++) {
                float s0 = acc[mt][nt][0], s1 = acc[mt][nt][1];
                float s2 = acc[mt][nt][2], s3 = acc[mt][nt][3];
                if (diag) {
                    const int c0i = nblk + nt * 8 + col2;
                    const int c1i = c0i + 1;
                    if (c0i == rAi) s0 = cA[mt];
                    if (c1i == rAi) s1 = cA[mt];
                    if (c0i == rBi) s2 = cB[mt];
                    if (c1i == rBi) s3 = cB[mt];
                }
                float g0 = ex2a(fmaf(s0, L2E, NEGS));
                float g1 = ex2a(fmaf(s1, L2E, NEGS));
                float g2 = ex2a(fmaf(s2, L2E, NEGS));
                float g3 = ex2a(fmaf(s3, L2E, NEGS));
                sumA[mt] += g0 + g1;
                sumB[mt] += g2 + g3;
                colp[nt][0] += g0 + g2;
                colp[nt][1] += g1 + g3;
            }
        }
        if (!diag) {
            #pragma unroll
            for (int nt = 0; nt < 8; nt++) {
                float c0 = colp[nt][0], c1 = colp[nt][1];
                c0 += __shfl_xor_sync(0xffffffffu, c0, 4);
                c0 += __shfl_xor_sync(0xffffffffu, c0, 8);
                c0 += __shfl_xor_sync(0xffffffffu, c0, 16);
                c1 += __shfl_xor_sync(0xffffffffu, c1, 4);
                c1 += __shfl_xor_sync(0xffffffffu, c1, 8);
                c1 += __shfl_xor_sync(0xffffffffu, c1, 16);
                if (lane < 4) {
                    float* dst = RSg + (size_t)b * N_ + j * 128 + nblk + nt * 8 + lane * 2;
                    atomicAdd(dst,     c0);
                    atomicAdd(dst + 1, c1);
                }
            }
        }
    }

    // own-row sums -> RSg
    {
        float* rsum = (float*)(sm + RS_OFF);
        __syncthreads();
        #pragma unroll
        for (int mt = 0; mt < 2; mt++) {
            float sA = sumA[mt], sB = sumB[mt];
            sA += __shfl_xor_sync(0xffffffffu, sA, 1);
            sA += __shfl_xor_sync(0xffffffffu, sA, 2);
            sB += __shfl_xor_sync(0xffffffffu, sB, 1);
            sB += __shfl_xor_sync(0xffffffffu, sB, 2);
            if ((lane & 3) == 0) {
                rsum[nhalf * 128 + mblk + mt * 16 + g4]     = sA;
                rsum[nhalf * 128 + mblk + mt * 16 + g4 + 8] = sB;
            }
        }
        __syncthreads();
        if (tid < TM)
            atomicAdd(&RSg[(size_t)b * N_ + r0 + tid], rsum[tid] + rsum[128 + tid]);
    }
    batch_barrier(&gbars[4 + b]);   // all of batch b's RSg final

    // ================= phase 2: full-precision normalize + mirror =================
    // A strip still resident in smem at A_OFF; dt=0 aliases it for B too.
    uint32_t al[2][4][4];
    #pragma unroll
    for (int ks = 0; ks < 4; ks++) {
        ldsm_x4(a_base0 + 128 + ks * 32, al[0][ks]);
        ldsm_x4(a_base1 + 128 + ks * 32, al[1][ks]);
    }

    float zrA[2], zrB[2];
    #pragma unroll
    for (int mt = 0; mt < 2; mt++) {
        zrA[mt] = rcpa(RSb[r0 + mblk + mt * 16 + g4]);
        zrB[mt] = rcpa(RSb[r0 + mblk + mt * 16 + g4 + 8]);
    }

    const size_t orow0 = (size_t)(b * N_ + r0 + mblk + g4) * N_;

    #pragma unroll 1
    for (int dt = 0; dt < ntile; dt++) {
        const int j = (i + dt) & 31;
        CP_WAIT(0);
        __syncthreads();
        if (dt + 1 < ntile) {
            const int jn = (i + dt + 1) & 31;
            stage_tile(sbase + (((dt + 1) & 1) ? B1_OFF : B0_OFF),
                       Xb + (size_t)jn * TN * 128, tid);
            stage_rs(sbase + (((dt + 1) & 1) ? RSB1_OFF : RSB0_OFF), RSb + jn * 128, tid);
            CP_COMMIT();
        }

        const uint32_t b_base = (dt == 0 ? sbase + A_OFF
                                         : sbase + ((dt & 1) ? B1_OFF : B0_OFF)) + bb_base;

        float acc[2][8][4];
        #pragma unroll
        for (int mt = 0; mt < 2; mt++)
            #pragma unroll
            for (int nt = 0; nt < 8; nt++)
                #pragma unroll
                for (int e = 0; e < 4; e++) acc[mt][nt][e] = 0.f;

        // full pipelined GEMM (hi.hi + lo.hi + hi.lo)
        uint32_t bbA[4][4], bbB[4][4];
        #pragma unroll
        for (int p = 0; p < 4; p++) ldsm_x4(b_base + (uint32_t)(p * 16) * LDST, bbA[p]);
        #pragma unroll
        for (int g = 0; g < 8; g++) {
            uint32_t (*cur)[4] = (g & 1) ? bbB : bbA;
            uint32_t (*nxt)[4] = (g & 1) ? bbA : bbB;
            if (g + 1 < 8) {
                const int gn = g + 1;
                const uint32_t off = (gn < 4) ? (uint32_t)(gn * 32)
                                              : (uint32_t)(128 + (gn - 4) * 32);
                #pragma unroll
                for (int p = 0; p < 4; p++)
                    ldsm_x4(b_base + (uint32_t)(p * 16) * LDST + off, nxt[p]);
            }
            if (g < 4) {
                const int ks = g;
                #pragma unroll
                for (int p = 0; p < 4; p++) {
                    mma16816(acc[0][2*p],   ah[0][ks], cur[p][0], cur[p][2]);
                    mma16816(acc[0][2*p+1], ah[0][ks], cur[p][1], cur[p][3]);
                    mma16816(acc[1][2*p],   ah[1][ks], cur[p][0], cur[p][2]);
                    mma16816(acc[1][2*p+1], ah[1][ks], cur[p][1], cur[p][3]);
                }
                #pragma unroll
                for (int p = 0; p < 4; p++) {
                    mma16816(acc[0][2*p],   al[0][ks], cur[p][0], cur[p][2]);
                    mma16816(acc[0][2*p+1], al[0][ks], cur[p][1], cur[p][3]);
                    mma16816(acc[1][2*p],   al[1][ks], cur[p][0], cur[p][2]);
                    mma16816(acc[1][2*p+1], al[1][ks], cur[p][1], cur[p][3]);
                }
            } else {
                const int ks = g - 4;
                #pragma unroll
                for (int p = 0; p < 4; p++) {
                    mma16816(acc[0][2*p],   ah[0][ks], cur[p][0], cur[p][2]);
                    mma16816(acc[0][2*p+1], ah[0][ks], cur[p][1], cur[p][3]);
                    mma16816(acc[1][2*p],   ah[1][ks], cur[p][0], cur[p][2]);
                    mma16816(acc[1][2*p+1], ah[1][ks], cur[p][1], cur[p][3]);
                }
            }
        }

        const bool diag = (dt == 0);
        const float* rsb = (const float*)(sm + ((dt & 1) ? RSB1_OFF : RSB0_OFF));
        const int colbase = j * 128 + nblk + col2;
        float* om = out + (size_t)(b * N_ + j * 128 + nblk + col2) * N_
                        + r0 + mblk + g4;
        #pragma unroll
        for (int nt = 0; nt < 8; nt++) {
            float zc0 = 0.f, zc1 = 0.f;
            if (!diag) {
                float2 rv = *(const float2*)&rsb[nblk + col2 + nt * 8];
                zc0 = rcpa(rv.x);
                zc1 = rcpa(rv.y);
            }
            #pragma unroll
            for (int mt = 0; mt < 2; mt++) {
                float g0 = ex2a(fmaf(acc[mt][nt][0], L2E, NEGS));
                float g1 = ex2a(fmaf(acc[mt][nt][1], L2E, NEGS));
                float g2 = ex2a(fmaf(acc[mt][nt][2], L2E, NEGS));
                float g3 = ex2a(fmaf(acc[mt][nt][3], L2E, NEGS));
                float* o1 = out + orow0 + (size_t)(mt * 16) * N_ + colbase + nt * 8;
                *(float2*)o1                    = make_float2(g0 * zrA[mt], g1 * zrA[mt]);
                *(float2*)(o1 + (size_t)8 * N_) = make_float2(g2 * zrB[mt], g3 * zrB[mt]);
                if (!diag) {
                    float* m1 = om + (size_t)(nt * 8) * N_ + mt * 16;
                    m1[0]       = g0 * zc0;
                    m1[N_]      = g1 * zc1;
                    m1[8]       = g2 * zc0;
                    m1[N_ + 8]  = g3 * zc1;
                }
            }
        }
    }
}

extern "C" void kernel_launch(void* const* d_in, const int* in_sizes, int n_in,
                              void* d_out, int out_size) {
    const float* X = (const float*)d_in[0];
    float* out = (float*)d_out;
    cudaFuncSetAttribute(fused_kernel,
                         cudaFuncAttributeMaxDynamicSharedMemorySize, SMEM_BYTES);
    fused_kernel<<<B_ * 32, 256, SMEM_BYTES>>>(X, out);
}